// round 9
// baseline (speedup 1.0000x reference)
#include <cuda_runtime.h>
#include <cstdint>

typedef unsigned long long ull;

// Packed fp32x2 FMA (sm_100+/sm_103a; ptxas never auto-generates this)
#define FMA2(d, a, b, c) \
    asm("fma.rn.f32x2 %0, %1, %2, %3;" : "=l"(d) : "l"(a), "l"(b), "l"(c))
#define ADD2(d, a, b) \
    asm("add.rn.f32x2 %0, %1, %2;" : "=l"(d) : "l"(a), "l"(b))

__device__ __forceinline__ ull pack2(float lo, float hi) {
    ull r; asm("mov.b64 %0, {%1, %2};" : "=l"(r) : "f"(lo), "f"(hi)); return r;
}
__device__ __forceinline__ void unpack2(ull v, float& lo, float& hi) {
    asm("mov.b64 {%0, %1}, %2;" : "=f"(lo), "=f"(hi) : "l"(v));
}

__device__ __forceinline__ void cp_async16cg(void* smem_dst, const void* gsrc) {
    unsigned s = (unsigned)__cvta_generic_to_shared(smem_dst);
    asm volatile("cp.async.cg.shared.global [%0], [%1], 16;" :: "r"(s), "l"(gsrc));
}
#define CP_COMMIT()  asm volatile("cp.async.commit_group;")
#define CP_WAIT(n)   asm volatile("cp.async.wait_group %0;" :: "n"(n))

// Problem constants
constexpr int B  = 8;
constexpr int C  = 256;
constexpr int M  = 64;
constexpr int H  = 128, W = 128, HW = H * W;       // input spatial
constexpr int KK = 25;                              // 5x5 window
constexpr int nH = 64, nW = 64, nHW = nH * nW;      // output spatial

// Scratch (device globals — no allocation allowed)
__device__ float g_mid[(size_t)B * M * HW];        // conv1x1 output (33.5 MB)
__device__ float g_ker[(size_t)B * KK * nHW];      // softmax kernel (3.3 MB)
__device__ float g_part[(size_t)2 * B * KK * nHW]; // k2 partial logits (6.6 MB)

// ---------------------------------------------------------------------------
// Kernel 1: 1x1 conv  C=256 -> M=64 + bias.  GEMM [64,256] x [256, B*HW].
// 3 blocks/SM (regs<=85): thread tile 8m x 4px (acc 16 ull).  Per cc-step:
// 2 broadcast LDS.128 (w) + 1 dense LDS.128 (x) + 4 movs + 16 FMA2.
// Per-chunk double-buffered weights (4KB, L2-hot refetch) + cp.async x.
// ---------------------------------------------------------------------------
constexpr int PT1 = 128;    // pixels per block
constexpr int KC1 = 16;     // channels per chunk

__global__ void __launch_bounds__(256, 3) k1_conv1x1(
    const float* __restrict__ x, const float* __restrict__ w1,
    const float* __restrict__ b1)
{
    __shared__ float  wch[2][KC1][64];       // 8 KB
    __shared__ float4 x_s[2][KC1][32];       // 16 KB  [buf][cc][p4]

    const int t    = threadIdx.x;
    const int bx   = blockIdx.x;             // 1024 blocks
    const int b    = bx >> 7;
    const int p0   = (bx & 127) * PT1;
    const int warp = t >> 5, lane = t & 31;
    const int m0   = warp * 8;
    const int px0  = lane * 4;

    const float* xb = x + (size_t)(b * C) * HW + p0;

    // x-fill roles: slot j=0 -> cc=t>>5 (0..7), j=1 -> cc=8+(t>>5); p4=(t&31)*4
    const int xccA = t >> 5;
    const int xccB = 8 + (t >> 5);
    const int xpf  = (t & 31) * 4;

    // ---- prologue: x chunks 0,1 via cp.async ----
    cp_async16cg(&x_s[0][xccA][t & 31], xb + (size_t)xccA * HW + xpf);
    cp_async16cg(&x_s[0][xccB][t & 31], xb + (size_t)xccB * HW + xpf);
    CP_COMMIT();
    cp_async16cg(&x_s[1][xccA][t & 31], xb + (size_t)(KC1 + xccA) * HW + xpf);
    cp_async16cg(&x_s[1][xccB][t & 31], xb + (size_t)(KC1 + xccB) * HW + xpf);
    CP_COMMIT();

    // ---- w prologue: stage chunk 0, prefetch chunk 1 into regs ----
    const int wm  = t & 63;
    const int wc4 = (t >> 6) * 4;
    {
        float4 w0 = *(const float4*)&w1[wm * C + wc4];
        wch[0][wc4 + 0][wm] = w0.x;
        wch[0][wc4 + 1][wm] = w0.y;
        wch[0][wc4 + 2][wm] = w0.z;
        wch[0][wc4 + 3][wm] = w0.w;
    }
    float4 wq = *(const float4*)&w1[wm * C + KC1 + wc4];

    ull acc[4][4];
#pragma unroll
    for (int i = 0; i < 4; i++)
#pragma unroll
        for (int p = 0; p < 4; p++) acc[i][p] = 0ULL;

    CP_WAIT(1);
    __syncthreads();

    int cur = 0;
#pragma unroll 1
    for (int ch = 0; ch < 16; ch++) {
        const int nxt = cur ^ 1;
        // stage w(ch+1) into nxt buffer; prefetch w(ch+2)
        if (ch < 15) {
            wch[nxt][wc4 + 0][wm] = wq.x;
            wch[nxt][wc4 + 1][wm] = wq.y;
            wch[nxt][wc4 + 2][wm] = wq.z;
            wch[nxt][wc4 + 3][wm] = wq.w;
            if (ch < 14)
                wq = *(const float4*)&w1[wm * C + (ch + 2) * KC1 + wc4];
        }
        // compute chunk ch from cur buffers
#pragma unroll
        for (int cc = 0; cc < KC1; cc++) {
            const float* wr = &wch[cur][cc][m0];
            ulonglong2 wv0 = *(const ulonglong2*)(wr);      // m-pairs 0,1
            ulonglong2 wv1 = *(const ulonglong2*)(wr + 4);  // m-pairs 2,3
            float4 xa = x_s[cur][cc][lane];
            ull xs0 = pack2(xa.x, xa.x);
            ull xs1 = pack2(xa.y, xa.y);
            ull xs2 = pack2(xa.z, xa.z);
            ull xs3 = pack2(xa.w, xa.w);
            FMA2(acc[0][0], wv0.x, xs0, acc[0][0]);
            FMA2(acc[0][1], wv0.x, xs1, acc[0][1]);
            FMA2(acc[0][2], wv0.x, xs2, acc[0][2]);
            FMA2(acc[0][3], wv0.x, xs3, acc[0][3]);
            FMA2(acc[1][0], wv0.y, xs0, acc[1][0]);
            FMA2(acc[1][1], wv0.y, xs1, acc[1][1]);
            FMA2(acc[1][2], wv0.y, xs2, acc[1][2]);
            FMA2(acc[1][3], wv0.y, xs3, acc[1][3]);
            FMA2(acc[2][0], wv1.x, xs0, acc[2][0]);
            FMA2(acc[2][1], wv1.x, xs1, acc[2][1]);
            FMA2(acc[2][2], wv1.x, xs2, acc[2][2]);
            FMA2(acc[2][3], wv1.x, xs3, acc[2][3]);
            FMA2(acc[3][0], wv1.y, xs0, acc[3][0]);
            FMA2(acc[3][1], wv1.y, xs1, acc[3][1]);
            FMA2(acc[3][2], wv1.y, xs2, acc[3][2]);
            FMA2(acc[3][3], wv1.y, xs3, acc[3][3]);
        }
        __syncthreads();
        if (ch < 14) {
            const int cnx = (ch + 2) * KC1;
            cp_async16cg(&x_s[cur][xccA][t & 31], xb + (size_t)(cnx + xccA) * HW + xpf);
            cp_async16cg(&x_s[cur][xccB][t & 31], xb + (size_t)(cnx + xccB) * HW + xpf);
            CP_COMMIT();
            CP_WAIT(1);
        } else {
            CP_WAIT(0);
        }
        __syncthreads();
        cur = nxt;
    }

    // ---- epilogue: bias + store ----
#pragma unroll
    for (int i = 0; i < 4; i++) {
        ull bp = pack2(b1[m0 + 2 * i], b1[m0 + 2 * i + 1]);
        float lo[4], hi[4];
#pragma unroll
        for (int p = 0; p < 4; p++) {
            ull v; ADD2(v, acc[i][p], bp);
            unpack2(v, lo[p], hi[p]);
        }
        size_t base = ((size_t)(b * M + m0 + 2 * i)) * HW + p0 + px0;
        *(float4*)&g_mid[base]      = make_float4(lo[0], lo[1], lo[2], lo[3]);
        *(float4*)&g_mid[base + HW] = make_float4(hi[0], hi[1], hi[2], hi[3]);
    }
}

// ---------------------------------------------------------------------------
// Kernel 2: 3x3 conv s2 p1, 64->25 — SPLIT over channel halves (2 blocks per
// output tile, 32 channels each) for 2x parallelism.  Partial logits to
// g_part; k2b reduces + bias + softmax.  Pipelined as in R7.
// ---------------------------------------------------------------------------
__global__ void __launch_bounds__(128) k2_encoder(
    const float* __restrict__ w2)
{
    __shared__ float2 ms[2][2][17][37];   // [buf][cpair][row][col]
    __shared__ float2 ws[2][2][9][26];    // [buf][cpair][j][k]

    const int t    = threadIdx.x;
    const int bz   = blockIdx.z;          // 16 = b*2 + half
    const int b    = bz >> 1;
    const int half = bz & 1;
    const int h0 = blockIdx.y * 8;
    const int w0 = blockIdx.x * 16;
    const int ty = t >> 4;
    const int tx = t & 15;
    const int cb = half * 32;             // channel base for this block

    constexpr int MS_BUF = 2 * 17 * 37;
    constexpr int WS_BUF = 2 * 9 * 26;
    float2* msb = &ms[0][0][0][0];
    float2* wsb = &ws[0][0][0][0];

    // ---- precompute fill slots (iteration-invariant) ----
    int ms_off[9], ms_di[9];
#pragma unroll
    for (int s = 0; s < 9; s++) {
        int idx = t + s * 128;
        ms_off[s] = -1; ms_di[s] = -1;
        if (idx < 1122) {
            int cp = idx / 561, r = idx % 561;
            int i = r / 33, jj = r % 33;
            int ih = 2 * h0 - 1 + i, iw = 2 * w0 - 1 + jj;
            ms_di[s] = (cp * 17 + i) * 37 + jj;
            if ((unsigned)ih < 128u && (unsigned)iw < 128u)
                ms_off[s] = (b * M + cb + 2 * cp) * HW + ih * W + iw;
        }
    }
    int ws_src[4], ws_di[4];
#pragma unroll
    for (int s = 0; s < 4; s++) {
        int idx = t + s * 128;
        ws_src[s] = -1; ws_di[s] = -1;
        if (idx < 450) {
            int cp = idx / 225, r = idx % 225;
            int j = r / 25, k = r % 25;
            ws_src[s] = (k * M + cb + 2 * cp) * 9 + j;
            ws_di[s] = (cp * 9 + j) * 26 + k;
        }
    }

    float2 mv[9], wvv[4];
#pragma unroll
    for (int s = 0; s < 9; s++) {
        mv[s] = make_float2(0.f, 0.f);
        if (ms_off[s] >= 0) {
            mv[s].x = g_mid[ms_off[s]];
            mv[s].y = g_mid[ms_off[s] + HW];
        }
    }
#pragma unroll
    for (int s = 0; s < 4; s++)
        if (ws_src[s] >= 0)
            wvv[s] = make_float2(w2[ws_src[s]], w2[ws_src[s] + 9]);
#pragma unroll
    for (int s = 0; s < 9; s++) if (ms_di[s] >= 0) msb[ms_di[s]] = mv[s];
#pragma unroll
    for (int s = 0; s < 4; s++) if (ws_di[s] >= 0) wsb[ws_di[s]] = wvv[s];
    __syncthreads();

    ull acc[25];
#pragma unroll
    for (int k = 0; k < 25; k++) acc[k] = 0ULL;

    int cur = 0;
#pragma unroll 1
    for (int chk = 0; chk < 8; chk++) {          // 8 chunks of 4 channels
        if (chk < 7) {
            const int moff = (chk + 1) * 4 * HW;
#pragma unroll
            for (int s = 0; s < 9; s++) {
                mv[s] = make_float2(0.f, 0.f);
                if (ms_off[s] >= 0) {
                    mv[s].x = g_mid[ms_off[s] + moff];
                    mv[s].y = g_mid[ms_off[s] + moff + HW];
                }
            }
            const int woff = (chk + 1) * 36;
#pragma unroll
            for (int s = 0; s < 4; s++)
                if (ws_src[s] >= 0)
                    wvv[s] = make_float2(w2[ws_src[s] + woff],
                                         w2[ws_src[s] + woff + 9]);
        }

#pragma unroll
        for (int cp = 0; cp < 2; cp++) {
            ull xp[9];
#pragma unroll
            for (int i = 0; i < 3; i++)
#pragma unroll
                for (int j = 0; j < 3; j++)
                    xp[i * 3 + j] = *(const ull*)&ms[cur][cp][2 * ty + i][2 * tx + j];
#pragma unroll
            for (int j9 = 0; j9 < 9; j9++) {
#pragma unroll
                for (int k2 = 0; k2 < 12; k2++) {
                    ulonglong2 wq = *(const ulonglong2*)&ws[cur][cp][j9][2 * k2];
                    FMA2(acc[2*k2  ], wq.x, xp[j9], acc[2*k2  ]);
                    FMA2(acc[2*k2+1], wq.y, xp[j9], acc[2*k2+1]);
                }
                ull wl = *(const ull*)&ws[cur][cp][j9][24];
                FMA2(acc[24], wl, xp[j9], acc[24]);
            }
        }

        if (chk < 7) {
            const int nb = cur ^ 1;
#pragma unroll
            for (int s = 0; s < 9; s++)
                if (ms_di[s] >= 0) msb[nb * MS_BUF + ms_di[s]] = mv[s];
#pragma unroll
            for (int s = 0; s < 4; s++)
                if (ws_di[s] >= 0) wsb[nb * WS_BUF + ws_di[s]] = wvv[s];
            __syncthreads();
        }
        cur ^= 1;
    }

    // partial logits (no bias/softmax)
    const int h = h0 + ty, w = w0 + tx;
    const size_t base = ((size_t)((half * B + b) * KK)) * nHW + h * nW + w;
#pragma unroll
    for (int k = 0; k < 25; k++) {
        float a, bq; unpack2(acc[k], a, bq);
        g_part[base + (size_t)k * nHW] = a + bq;
    }
}

// k2b: sum halves + bias + softmax -> g_ker
__global__ void __launch_bounds__(256) k2b_softmax(const float* __restrict__ b2)
{
    const int P  = blockIdx.x * 256 + threadIdx.x;   // 32768 px
    const int b  = P >> 12;
    const int hw = P & 4095;

    float lg[25];
#pragma unroll
    for (int k = 0; k < 25; k++) {
        size_t o0 = ((size_t)(b * KK + k)) * nHW + hw;
        lg[k] = g_part[o0] + g_part[(size_t)B * KK * nHW + o0] + b2[k];
    }
    float mx = lg[0];
#pragma unroll
    for (int k = 1; k < 25; k++) mx = fmaxf(mx, lg[k]);
    float e[25], sum = 0.f;
#pragma unroll
    for (int k = 0; k < 25; k++) { e[k] = __expf(lg[k] - mx); sum += e[k]; }
    const float inv = 1.f / sum;
#pragma unroll
    for (int k = 0; k < 25; k++)
        g_ker[((size_t)(b * KK + k)) * nHW + hw] = e[k] * inv;
}

// ---------------------------------------------------------------------------
// Kernel 3: softmax-weighted 5x5 window sum (UNCHANGED from R7).
// ---------------------------------------------------------------------------
__global__ void __launch_bounds__(256) k3_apply(
    const float* __restrict__ x, float* __restrict__ out)
{
    __shared__ float2 xi[2][2][35][38];

    const int t  = threadIdx.x;
    const int bz = blockIdx.z;
    const int b  = bz >> 2;
    const int cbase = (bz & 3) * 64;
    const int h0 = blockIdx.y * 16, w0 = blockIdx.x * 16;
    const int py = t >> 4, px = t & 15;
    const int h = h0 + py, w = w0 + px;

    constexpr int XI_BUF = 2 * 35 * 38;
    float2* xib = &xi[0][0][0][0];

    ull kp[25];
#pragma unroll
    for (int k = 0; k < 25; k++) {
        float kv = g_ker[((size_t)(b * KK + k)) * nHW + h * nW + w];
        kp[k] = pack2(kv, kv);
    }

    const int ir0 = 2 * h0 - 2, ic0 = 2 * w0 - 2;
    const float* xb = x + ((size_t)(b * C + cbase)) * HW;

    int xoff[10], xdi[10];
#pragma unroll
    for (int s = 0; s < 10; s++) {
        int idx = t + s * 256;
        xoff[s] = -1; xdi[s] = -1;
        if (idx < 2450) {
            int cp = (idx >= 1225) ? 1 : 0;
            int rr = idx - cp * 1225;
            int r = rr / 35, cc = rr - r * 35;
            int ir = ir0 + r, ic = ic0 + cc;
            xdi[s] = (cp * 35 + r) * 38 + cc;
            if ((unsigned)ir < 128u && (unsigned)ic < 128u)
                xoff[s] = cp * 2 * HW + ir * W + ic;
        }
    }

    float2 xv[10];
#pragma unroll
    for (int s = 0; s < 10; s++) {
        xv[s] = make_float2(0.f, 0.f);
        if (xoff[s] >= 0) {
            xv[s].x = xb[xoff[s]];
            xv[s].y = xb[xoff[s] + HW];
        }
    }
#pragma unroll
    for (int s = 0; s < 10; s++) if (xdi[s] >= 0) xib[xdi[s]] = xv[s];
    __syncthreads();

    int cur = 0;
#pragma unroll 1
    for (int it = 0; it < 16; it++) {
        if (it < 15) {
            const int coff = (it + 1) * 4 * HW;
#pragma unroll
            for (int s = 0; s < 10; s++) {
                xv[s] = make_float2(0.f, 0.f);
                if (xoff[s] >= 0) {
                    xv[s].x = xb[xoff[s] + coff];
                    xv[s].y = xb[xoff[s] + coff + HW];
                }
            }
        }

        const int c = cbase + it * 4;
#pragma unroll
        for (int cp = 0; cp < 2; cp++) {
            ull a[5];
#pragma unroll
            for (int i = 0; i < 5; i++) a[i] = 0ULL;
#pragma unroll
            for (int i = 0; i < 5; i++)
#pragma unroll
                for (int j = 0; j < 5; j++) {
                    ull xvv = *(const ull*)&xi[cur][cp][2 * py + i][2 * px + j];
                    const int k = i * 5 + j;
                    FMA2(a[k % 5], kp[k], xvv, a[k % 5]);
                }
            ull s01, s23, ssum;
            ADD2(s01, a[0], a[1]);
            ADD2(s23, a[2], a[3]);
            ADD2(s01, s01, s23);
            ADD2(ssum, s01, a[4]);
            float o0, o1; unpack2(ssum, o0, o1);
            const size_t obase = ((size_t)(b * C + c + 2 * cp)) * nHW + h * nW + w;
            out[obase]       = o0;
            out[obase + nHW] = o1;
        }

        if (it < 15) {
            const int nb = cur ^ 1;
#pragma unroll
            for (int s = 0; s < 10; s++)
                if (xdi[s] >= 0) xib[nb * XI_BUF + xdi[s]] = xv[s];
            __syncthreads();
        }
        cur ^= 1;
    }
}

// ---------------------------------------------------------------------------
extern "C" void kernel_launch(void* const* d_in, const int* in_sizes, int n_in,
                              void* d_out, int out_size)
{
    (void)in_sizes; (void)n_in; (void)out_size;
    const float* x  = (const float*)d_in[0];
    const float* w1 = (const float*)d_in[1];
    const float* b1 = (const float*)d_in[2];
    const float* w2 = (const float*)d_in[3];
    const float* b2 = (const float*)d_in[4];
    float* out = (float*)d_out;

    k1_conv1x1<<<1024, 256>>>(x, w1, b1);
    k2_encoder<<<dim3(4, 8, 16), 128>>>(w2);
    k2b_softmax<<<128, 256>>>(b2);
    k3_apply<<<dim3(4, 4, 32), 256>>>(x, out);
}